// round 12
// baseline (speedup 1.0000x reference)
#include <cuda_runtime.h>

#define SEQ    2048
#define DIM    256
#define NHEAD  8
#define NBATCH 8
#define NROWS  (NBATCH*SEQ)     // 16384
#define HBTOT  (NHEAD*NBATCH)   // 64

typedef unsigned long long ull;

// scratch: q,k,v  each [H*B][S][D] fp32 = 128 MB
__device__ float g_q[(size_t)HBTOT*SEQ*DIM];
__device__ float g_k[(size_t)HBTOT*SEQ*DIM];
__device__ float g_v[(size_t)HBTOT*SEQ*DIM];

// ---------------------------------------------------------------------------
// packed f32x2 helpers (FFMA2 path: only reachable via PTX fma.rn.f32x2)
// ---------------------------------------------------------------------------
__device__ __forceinline__ ull pk2(float lo, float hi) {
    ull r; asm("mov.b64 %0, {%1,%2};" : "=l"(r) : "f"(lo), "f"(hi)); return r;
}
__device__ __forceinline__ void upk2(ull v, float& lo, float& hi) {
    asm("mov.b64 {%0,%1}, %2;" : "=f"(lo), "=f"(hi) : "l"(v));
}
__device__ __forceinline__ ull ffma2(ull a, ull b, ull c) {
    ull d; asm("fma.rn.f32x2 %0, %1, %2, %3;" : "=l"(d) : "l"(a), "l"(b), "l"(c));
    return d;
}
__device__ __forceinline__ ull fmul2(ull a, ull b) {
    ull d; asm("mul.rn.f32x2 %0, %1, %2;" : "=l"(d) : "l"(a), "l"(b));
    return d;
}
__device__ __forceinline__ void cpa16(void* dst, const void* src) {
    unsigned s = (unsigned)__cvta_generic_to_shared(dst);
    asm volatile("cp.async.cg.shared.global [%0], [%1], 16;" :: "r"(s), "l"(src));
}

// ---------------------------------------------------------------------------
// Kernel 0: init output with bias (flash accumulates into it atomically)
// ---------------------------------------------------------------------------
__global__ __launch_bounds__(256) void init_out_kernel(
    const float* __restrict__ Cb, float* __restrict__ out)
{
    int idx = blockIdx.x * 256 + threadIdx.x;     // 0..131071
    out[idx] = Cb[idx & 7];
}

// ---------------------------------------------------------------------------
// Kernel 1: QKV projections.  out[h,r,d] = sum_f A[r,f]*W[h,f,d] + b[h,d]
// 128x128 output tile per CTA, 8 rows x (4+4) cols per thread, K-chunks of 16.
// Thread columns are tx*4 and tx*4+64 -> B LDS.128 at 16B lane stride
// (conflict-light), unlike tx*8 which was 4-way conflicted (R11 regression).
// A staged in smem PRE-DUPLICATED as (a,a) ull pairs -> broadcast LDS.64.
// B chunks double-buffered cp.async; A chunks LDG (1 chunk ahead) -> dup STS.
// grid (2 col-tiles, 128 row-tiles, 24 matrices), block (16,16), 2 CTAs/SM.
// ---------------------------------------------------------------------------
#define PROJ_SMEM (2*16*128*8 + 2*16*128*4)   // As2 32KB + Bs 16KB = 49152

__global__ __launch_bounds__(256, 2) void proj_kernel(
    const float* __restrict__ x, const float* __restrict__ lstm,
    const float* __restrict__ Qw, const float* __restrict__ Qb,
    const float* __restrict__ Kw, const float* __restrict__ Kb,
    const float* __restrict__ Vw, const float* __restrict__ Vb)
{
    extern __shared__ ull smraw[];
    ull*   As2 = smraw;                       // [2][16][128] dup'd pairs
    float* Bs  = (float*)(smraw + 2*16*128);  // [2][16][128]

    const int bz = blockIdx.z;
    const int type = bz >> 3, h = bz & 7;
    const float* A; const float* W; const float* bias; float* out;
    if (type == 0)      { A = lstm; W = Qw; bias = Qb; out = g_q; }
    else if (type == 1) { A = x;    W = Kw; bias = Kb; out = g_k; }
    else                { A = x;    W = Vw; bias = Vb; out = g_v; }
    W    += h * DIM * DIM;
    bias += h * DIM;
    out  += (size_t)h * NROWS * DIM;

    const int r0 = blockIdx.y * 128, d0 = blockIdx.x * 128;
    const int tx = threadIdx.x, ty = threadIdx.y;
    const int tid = ty * 16 + tx;

    // A chunk = 128 rows x 16 cols = 512 float4 tasks (tid, tid+256)
    const int arow0 = tid >> 2,         aseg0 = (tid & 3) * 4;
    const int arow1 = (tid + 256) >> 2, aseg1 = aseg0;

    float4 ra0, ra1;        // current prefetched A chunk

    // B chunk = 16 rows x 128 cols = 512 float4 tasks (tid, tid+256)
    const int brow  = tid >> 5,         bseg = (tid & 31) * 4;   // rows 0..7
    const int brow2 = (tid + 256) >> 5;                          // rows 8..15

    auto ldg_a = [&](int kt, float4& v0, float4& v1) {
        v0 = *(const float4*)&A[(size_t)(r0 + arow0) * DIM + kt + aseg0];
        v1 = *(const float4*)&A[(size_t)(r0 + arow1) * DIM + kt + aseg1];
    };
    auto cpa_b = [&](int buf, int kt) {
        cpa16(&Bs[(buf * 16 + brow)  * 128 + bseg],
              &W[(size_t)(kt + brow)  * DIM + d0 + bseg]);
        cpa16(&Bs[(buf * 16 + brow2) * 128 + bseg],
              &W[(size_t)(kt + brow2) * DIM + d0 + bseg]);
    };
    auto sts_a = [&](int buf, float4 v0, float4 v1) {
        ull* p0 = &As2[(size_t)buf * 16 * 128 + arow0];
        p0[(aseg0 + 0) * 128] = pk2(v0.x, v0.x);
        p0[(aseg0 + 1) * 128] = pk2(v0.y, v0.y);
        p0[(aseg0 + 2) * 128] = pk2(v0.z, v0.z);
        p0[(aseg0 + 3) * 128] = pk2(v0.w, v0.w);
        ull* p1 = &As2[(size_t)buf * 16 * 128 + arow1];
        p1[(aseg1 + 0) * 128] = pk2(v1.x, v1.x);
        p1[(aseg1 + 1) * 128] = pk2(v1.y, v1.y);
        p1[(aseg1 + 2) * 128] = pk2(v1.z, v1.z);
        p1[(aseg1 + 3) * 128] = pk2(v1.w, v1.w);
    };

    ull acc[8][4];          // [row i][col pair: tx*4+{0,2}, 64+tx*4+{0,2}]
    #pragma unroll
    for (int i = 0; i < 8; i++)
        #pragma unroll
        for (int j = 0; j < 4; j++) acc[i][j] = 0ull;

    // prologue: chunk 0 in flight
    ldg_a(0, ra0, ra1);
    cpa_b(0, 0);
    asm volatile("cp.async.commit_group;");

    for (int ck = 0; ck < 16; ck++) {
        const int buf = ck & 1;
        sts_a(buf, ra0, ra1);                     // dup-store A chunk ck
        asm volatile("cp.async.wait_group 0;");   // B chunk ck landed
        __syncthreads();                          // all warps done with buf^1

        if (ck < 15) {                            // prefetch chunk ck+1
            ldg_a((ck + 1) * 16, ra0, ra1);       // latency covered by compute
            cpa_b(buf ^ 1, (ck + 1) * 16);
            asm volatile("cp.async.commit_group;");
        }

        const ull*   ap = &As2[(size_t)buf * 16 * 128 + ty * 8];
        const float* bp = &Bs[(size_t)buf * 16 * 128 + tx * 4];
        #pragma unroll
        for (int kk = 0; kk < 16; kk++) {
            ulonglong2 b01 = *(const ulonglong2*)&bp[kk * 128];       // cols tx*4..+3
            ulonglong2 b23 = *(const ulonglong2*)&bp[kk * 128 + 64];  // cols 64+tx*4..+3
            #pragma unroll
            for (int i = 0; i < 8; i++) {
                ull a = ap[kk * 128 + i];
                acc[i][0] = ffma2(a, b01.x, acc[i][0]);
                acc[i][1] = ffma2(a, b01.y, acc[i][1]);
                acc[i][2] = ffma2(a, b23.x, acc[i][2]);
                acc[i][3] = ffma2(a, b23.y, acc[i][3]);
            }
        }
        __syncthreads();   // compute done before buf overwritten next iter
    }

    // epilogue: unpack, add bias, store 8 rows x (4+4) cols
    float bv0[4], bv1[4];
    #pragma unroll
    for (int n = 0; n < 4; n++) {
        bv0[n] = bias[d0 + tx * 4 + n];
        bv1[n] = bias[d0 + 64 + tx * 4 + n];
    }
    #pragma unroll
    for (int i = 0; i < 8; i++) {
        float v[8];
        upk2(acc[i][0], v[0], v[1]);
        upk2(acc[i][1], v[2], v[3]);
        upk2(acc[i][2], v[4], v[5]);
        upk2(acc[i][3], v[6], v[7]);
        float* dst = &out[(size_t)(r0 + ty * 8 + i) * DIM + d0 + tx * 4];
        float4 o0 = make_float4(v[0] + bv0[0], v[1] + bv0[1], v[2] + bv0[2], v[3] + bv0[3]);
        float4 o1 = make_float4(v[4] + bv1[0], v[5] + bv1[1], v[6] + bv1[2], v[7] + bv1[3]);
        *(float4*)&dst[0]  = o0;
        *(float4*)&dst[64] = o1;
    }
}

// ---------------------------------------------------------------------------
// Kernel 2: flash attention with SPARSE softmax/PV + fused final projection.
// (unchanged from R9 — protect the win)
// ---------------------------------------------------------------------------
#define FLASH_SMEM (3*64*256*4)   // 196608 bytes

__global__ __launch_bounds__(256, 1) void flash_kernel(
    const float* __restrict__ Cw, float* __restrict__ out)
{
    extern __shared__ float sm[];
    float* Qs = sm;               // [64][256] linear
    float* K0 = sm + 64 * 256;    // two [64][256] xor-swizzled buffers

    const int qt = blockIdx.x;    // 0..31
    const int hb = blockIdx.y;    // 0..63
    const size_t base = (size_t)hb * SEQ * DIM;
    const int tid = threadIdx.x;
    const int w = tid >> 5, c = tid & 31;
    const int cx = c & 7;

    // prefetch K tile 0 (async), then load Q tile 64x256
    #pragma unroll
    for (int i = 0; i < 16; i++) {
        int u = tid + i * 256;
        int r = u >> 6, k4 = u & 63;
        cpa16(&K0[r * 256 + ((k4 ^ (r & 7)) << 2)],
              &g_k[base + (size_t)r * DIM + k4 * 4]);
    }
    asm volatile("cp.async.commit_group;");

    #pragma unroll
    for (int i = 0; i < 16; i++) {
        int u = tid + i * 256;
        int r = u >> 6, k4 = u & 63;
        *(float4*)&Qs[r * 256 + k4 * 4] =
            *(const float4*)&g_q[base + (size_t)(qt * 64 + r) * DIM + k4 * 4];
    }

    ull o[8][4];                  // packed pairs covering dims 8c..8c+7
    #pragma unroll
    for (int i = 0; i < 8; i++)
        #pragma unroll
        for (int j = 0; j < 4; j++) o[i][j] = 0ull;
    float m[8], l[8];
    #pragma unroll
    for (int i = 0; i < 8; i++) { m[i] = -3.0e38f; l[i] = 0.f; }

    int buf = 0;
    for (int kt = 0; kt < SEQ / 64; kt++) {
        asm volatile("cp.async.wait_group 0;");
        __syncthreads();          // current K buffer visible; prev reads done

        if (kt + 1 < SEQ / 64) {  // prefetch next tile into other buffer
            float* Kn = K0 + (buf ^ 1) * 64 * 256;
            #pragma unroll
            for (int i = 0; i < 16; i++) {
                int u = tid + i * 256;
                int r = u >> 6, k4 = u & 63;
                cpa16(&Kn[r * 256 + ((k4 ^ (r & 7)) << 2)],
                      &g_k[base + (size_t)((kt + 1) * 64 + r) * DIM + k4 * 4]);
            }
            asm volatile("cp.async.commit_group;");
        }

        const float* Kc = K0 + buf * 64 * 256;

        // dense QK: lane computes s[rr][col c] and s[rr][col c+32]
        ull acc[8][2];
        #pragma unroll
        for (int rr = 0; rr < 8; rr++) { acc[rr][0] = 0ull; acc[rr][1] = 0ull; }

        const float* k0p = &Kc[c * 256];
        const float* k1p = &Kc[(c + 32) * 256];   // same xor phase: (c+32)&7==c&7
        #pragma unroll 4
        for (int k4 = 0; k4 < 64; k4++) {
            int sc = (k4 ^ cx) << 2;
            ulonglong2 kv0 = *(const ulonglong2*)&k0p[sc];
            ulonglong2 kv1 = *(const ulonglong2*)&k1p[sc];
            #pragma unroll
            for (int rr = 0; rr < 8; rr++) {
                ulonglong2 qv = *(const ulonglong2*)&Qs[(w * 8 + rr) * 256 + k4 * 4];
                acc[rr][0] = ffma2(qv.x, kv0.x, acc[rr][0]);
                acc[rr][0] = ffma2(qv.y, kv0.y, acc[rr][0]);
                acc[rr][1] = ffma2(qv.x, kv1.x, acc[rr][1]);
                acc[rr][1] = ffma2(qv.y, kv1.y, acc[rr][1]);
            }
        }

        // sparse softmax + PV gather, per row
        const float* vtile = &g_v[base + (size_t)(kt * 64) * DIM + c * 8];
        #pragma unroll
        for (int rr = 0; rr < 8; rr++) {
            float a, b;
            upk2(acc[rr][0], a, b); float s0 = (a + b) * 0.0625f;
            upk2(acc[rr][1], a, b); float s1 = (a + b) * 0.0625f;
            float tm = fmaxf(s0, s1);
            #pragma unroll
            for (int off = 16; off > 0; off >>= 1)
                tm = fmaxf(tm, __shfl_xor_sync(0xffffffffu, tm, off));

            if (tm >= m[rr] - 35.0f) {            // warp-uniform
                float nm = fmaxf(m[rr], tm);
                if (nm > m[rr]) {                 // rescale only on max update
                    float fac = __expf(m[rr] - nm);
                    l[rr] *= fac;
                    ull f2 = pk2(fac, fac);
                    o[rr][0] = fmul2(o[rr][0], f2);
                    o[rr][1] = fmul2(o[rr][1], f2);
                    o[rr][2] = fmul2(o[rr][2], f2);
                    o[rr][3] = fmul2(o[rr][3], f2);
                    m[rr] = nm;
                }
                float thr = nm - 35.0f;
                unsigned b0 = __ballot_sync(0xffffffffu, s0 >= thr);
                unsigned b1 = __ballot_sync(0xffffffffu, s1 >= thr);
                while (b0) {
                    int ln = __ffs(b0) - 1; b0 &= b0 - 1;
                    float sv = __shfl_sync(0xffffffffu, s0, ln);
                    float p = __expf(sv - nm);
                    l[rr] += p;
                    const ulonglong2* vr =
                        (const ulonglong2*)(vtile + (size_t)ln * DIM);
                    ulonglong2 V0 = vr[0], V1 = vr[1];
                    ull pp = pk2(p, p);
                    o[rr][0] = ffma2(pp, V0.x, o[rr][0]);
                    o[rr][1] = ffma2(pp, V0.y, o[rr][1]);
                    o[rr][2] = ffma2(pp, V1.x, o[rr][2]);
                    o[rr][3] = ffma2(pp, V1.y, o[rr][3]);
                }
                while (b1) {
                    int ln = __ffs(b1) - 1; b1 &= b1 - 1;
                    float sv = __shfl_sync(0xffffffffu, s1, ln);
                    float p = __expf(sv - nm);
                    l[rr] += p;
                    const ulonglong2* vr =
                        (const ulonglong2*)(vtile + (size_t)(ln + 32) * DIM);
                    ulonglong2 V0 = vr[0], V1 = vr[1];
                    ull pp = pk2(p, p);
                    o[rr][0] = ffma2(pp, V0.x, o[rr][0]);
                    o[rr][1] = ffma2(pp, V0.y, o[rr][1]);
                    o[rr][2] = ffma2(pp, V1.x, o[rr][2]);
                    o[rr][3] = ffma2(pp, V1.y, o[rr][3]);
                }
            }
        }
        buf ^= 1;
    }

    // ------------------------------------------------------------------
    // fused epilogue: out[r,n] += sum_d o_norm[r,d] * Cw[h*256+d, n]
    // ------------------------------------------------------------------
    const int h = hb >> 3;
    const int out_r0 = (hb & 7) * SEQ + qt * 64 + w * 8;

    float cw[8][8];               // [i dim-in-slice][n]
    const float* cwp = Cw + ((size_t)h * 256 + c * 8) * 8;
    #pragma unroll
    for (int i = 0; i < 8; i++) {
        float4 u0 = *(const float4*)&cwp[i * 8 + 0];
        float4 u1 = *(const float4*)&cwp[i * 8 + 4];
        cw[i][0] = u0.x; cw[i][1] = u0.y; cw[i][2] = u0.z; cw[i][3] = u0.w;
        cw[i][4] = u1.x; cw[i][5] = u1.y; cw[i][6] = u1.z; cw[i][7] = u1.w;
    }

    #pragma unroll
    for (int rr = 0; rr < 8; rr++) {
        float inv = 1.0f / l[rr];
        float v[8];
        upk2(o[rr][0], v[0], v[1]);
        upk2(o[rr][1], v[2], v[3]);
        upk2(o[rr][2], v[4], v[5]);
        upk2(o[rr][3], v[6], v[7]);
        float pn[8] = {};
        #pragma unroll
        for (int i = 0; i < 8; i++) {
            float ov = v[i] * inv;
            #pragma unroll
            for (int n = 0; n < 8; n++)
                pn[n] = fmaf(ov, cw[i][n], pn[n]);
        }
        #pragma unroll
        for (int n = 0; n < 8; n++) {
            #pragma unroll
            for (int off = 16; off > 0; off >>= 1)
                pn[n] += __shfl_xor_sync(0xffffffffu, pn[n], off);
        }
        if (c < 8)
            atomicAdd(&out[(size_t)(out_r0 + rr) * 8 + c], pn[c]);
    }
}

// ---------------------------------------------------------------------------
extern "C" void kernel_launch(void* const* d_in, const int* in_sizes, int n_in,
                              void* d_out, int out_size)
{
    const float* x    = (const float*)d_in[0];
    const float* lstm = (const float*)d_in[1];
    const float* Qw   = (const float*)d_in[2];
    const float* Qb   = (const float*)d_in[3];
    const float* Kw   = (const float*)d_in[4];
    const float* Kb   = (const float*)d_in[5];
    const float* Vw   = (const float*)d_in[6];
    const float* Vb   = (const float*)d_in[7];
    const float* Cw   = (const float*)d_in[8];
    const float* Cb   = (const float*)d_in[9];
    float* out = (float*)d_out;

    cudaFuncSetAttribute(proj_kernel,  cudaFuncAttributeMaxDynamicSharedMemorySize, PROJ_SMEM);
    cudaFuncSetAttribute(flash_kernel, cudaFuncAttributeMaxDynamicSharedMemorySize, FLASH_SMEM);

    init_out_kernel<<<512, 256>>>(Cb, out);     // out[r,n] = Cb[n]
    proj_kernel<<<dim3(2, 128, 24), dim3(16, 16), PROJ_SMEM>>>(
        x, lstm, Qw, Qb, Kw, Kb, Vw, Vb);
    flash_kernel<<<dim3(32, 64), 256, FLASH_SMEM>>>(Cw, out);
}

// round 13
// speedup vs baseline: 1.7942x; 1.7942x over previous
#include <cuda_runtime.h>

#define SEQ    2048
#define DIM    256
#define NHEAD  8
#define NBATCH 8
#define NROWS  (NBATCH*SEQ)     // 16384
#define HBTOT  (NHEAD*NBATCH)   // 64

typedef unsigned long long ull;

// scratch: q,k,v  each [H*B][S][D] fp32 = 128 MB
__device__ float g_q[(size_t)HBTOT*SEQ*DIM];
__device__ float g_k[(size_t)HBTOT*SEQ*DIM];
__device__ float g_v[(size_t)HBTOT*SEQ*DIM];

// ---------------------------------------------------------------------------
// packed f32x2 helpers (FFMA2 path: only reachable via PTX fma.rn.f32x2)
// ---------------------------------------------------------------------------
__device__ __forceinline__ ull pk2(float lo, float hi) {
    ull r; asm("mov.b64 %0, {%1,%2};" : "=l"(r) : "f"(lo), "f"(hi)); return r;
}
__device__ __forceinline__ void upk2(ull v, float& lo, float& hi) {
    asm("mov.b64 {%0,%1}, %2;" : "=f"(lo), "=f"(hi) : "l"(v));
}
__device__ __forceinline__ ull ffma2(ull a, ull b, ull c) {
    ull d; asm("fma.rn.f32x2 %0, %1, %2, %3;" : "=l"(d) : "l"(a), "l"(b), "l"(c));
    return d;
}
__device__ __forceinline__ ull fmul2(ull a, ull b) {
    ull d; asm("mul.rn.f32x2 %0, %1, %2;" : "=l"(d) : "l"(a), "l"(b));
    return d;
}
__device__ __forceinline__ void cpa16(void* dst, const void* src) {
    unsigned s = (unsigned)__cvta_generic_to_shared(dst);
    asm volatile("cp.async.cg.shared.global [%0], [%1], 16;" :: "r"(s), "l"(src));
}

// ---------------------------------------------------------------------------
// Kernel 0: init output with bias (flash accumulates into it atomically)
// ---------------------------------------------------------------------------
__global__ __launch_bounds__(256) void init_out_kernel(
    const float* __restrict__ Cb, float* __restrict__ out)
{
    int idx = blockIdx.x * 256 + threadIdx.x;     // 0..131071
    out[idx] = Cb[idx & 7];
}

// ---------------------------------------------------------------------------
// Kernel 1: QKV projections (R9 version — last known good).
// grid: (4 n-tiles, 256 m-tiles, 24 matrices), block 16x16, 64x64 tile.
// K-chunks of 32, cp.async double-buffered (loads overlap compute).
// ---------------------------------------------------------------------------
__global__ __launch_bounds__(256) void proj_kernel(
    const float* __restrict__ x, const float* __restrict__ lstm,
    const float* __restrict__ Qw, const float* __restrict__ Qb,
    const float* __restrict__ Kw, const float* __restrict__ Kb,
    const float* __restrict__ Vw, const float* __restrict__ Vb)
{
    __shared__ float As[2][64][32];   // [buf][row][k]
    __shared__ float Bs[2][32][64];   // [buf][k][col]

    const int bz = blockIdx.z;
    const int type = bz >> 3, h = bz & 7;
    const float* A; const float* W; const float* bias; float* out;
    if (type == 0)      { A = lstm; W = Qw; bias = Qb; out = g_q; }
    else if (type == 1) { A = x;    W = Kw; bias = Kb; out = g_k; }
    else                { A = x;    W = Vw; bias = Vb; out = g_v; }
    W    += h * DIM * DIM;
    bias += h * DIM;
    out  += (size_t)h * NROWS * DIM;

    const int r0 = blockIdx.y * 64, d0 = blockIdx.x * 64;
    const int tx = threadIdx.x, ty = threadIdx.y;
    const int tid = ty * 16 + tx;

    // cp.async load of one 64x32 A chunk + 32x64 B chunk into buffer `buf`
    auto load_chunk = [&](int buf, int kt) {
        #pragma unroll
        for (int i = 0; i < 2; i++) {
            int u = tid + i * 256;                // 0..511
            int ar = u >> 3, as = (u & 7) * 4;    // A: row, 4-float seg
            cpa16(&As[buf][ar][as],
                  &A[(size_t)(r0 + ar) * DIM + kt + as]);
            int br = u >> 4, bs = (u & 15) * 4;   // B: k-row, 4-float seg
            cpa16(&Bs[buf][br][bs],
                  &W[(size_t)(kt + br) * DIM + d0 + bs]);
        }
    };

    ull acc[4][2];
    #pragma unroll
    for (int i = 0; i < 4; i++) { acc[i][0] = 0ull; acc[i][1] = 0ull; }

    load_chunk(0, 0);
    asm volatile("cp.async.commit_group;");

    int buf = 0;
    for (int ck = 0; ck < 8; ck++) {
        if (ck + 1 < 8) {
            load_chunk(buf ^ 1, (ck + 1) * 32);
            asm volatile("cp.async.commit_group;");
            asm volatile("cp.async.wait_group 1;");
        } else {
            asm volatile("cp.async.wait_group 0;");
        }
        __syncthreads();

        #pragma unroll
        for (int kk = 0; kk < 32; kk++) {
            float a0 = As[buf][ty * 4 + 0][kk];
            float a1 = As[buf][ty * 4 + 1][kk];
            float a2 = As[buf][ty * 4 + 2][kk];
            float a3 = As[buf][ty * 4 + 3][kk];
            ulonglong2 bv = *(const ulonglong2*)&Bs[buf][kk][tx * 4];
            ull p0 = pk2(a0, a0), p1 = pk2(a1, a1);
            ull p2 = pk2(a2, a2), p3 = pk2(a3, a3);
            acc[0][0] = ffma2(p0, bv.x, acc[0][0]);
            acc[0][1] = ffma2(p0, bv.y, acc[0][1]);
            acc[1][0] = ffma2(p1, bv.x, acc[1][0]);
            acc[1][1] = ffma2(p1, bv.y, acc[1][1]);
            acc[2][0] = ffma2(p2, bv.x, acc[2][0]);
            acc[2][1] = ffma2(p2, bv.y, acc[2][1]);
            acc[3][0] = ffma2(p3, bv.x, acc[3][0]);
            acc[3][1] = ffma2(p3, bv.y, acc[3][1]);
        }
        __syncthreads();   // compute done before buf is overwritten next iter
        buf ^= 1;
    }

    #pragma unroll
    for (int i = 0; i < 4; i++) {
        float4 o;
        upk2(acc[i][0], o.x, o.y);
        upk2(acc[i][1], o.z, o.w);
        o.x += bias[d0 + tx * 4 + 0];
        o.y += bias[d0 + tx * 4 + 1];
        o.z += bias[d0 + tx * 4 + 2];
        o.w += bias[d0 + tx * 4 + 3];
        *(float4*)&out[(size_t)(r0 + ty * 4 + i) * DIM + d0 + tx * 4] = o;
    }
}

// ---------------------------------------------------------------------------
// Kernel 2: flash attention, 128-wide K tiles (4 score cols per lane).
// grid (32 q-tiles, 64 hb), 256 threads.  Warp w owns q rows w*8..w*8+7;
// lane c owns tile-cols c, c+32, c+64, c+96 -> Q broadcasts amortized 4x,
// making the QK loop fma-pipe-bound (smem 192 cyc vs fma 256 cyc per SM/k4).
// Per-column math identical to the 64-wide version (same FFMA2 chains).
// Single 128KB K buffer; next tile's cp.async issued after the post-QK
// barrier, overlapping the sparse softmax/PV phase (which reads only
// registers + g_v).  Sparse gather: candidates (s >= m-35) only.
// ---------------------------------------------------------------------------
#define FLASH_SMEM ((64*256 + 128*256) * 4)   // Q 64KB + K 128KB = 196608

__global__ __launch_bounds__(256, 1) void flash_kernel(
    const float* __restrict__ Cw, float* __restrict__ out)
{
    extern __shared__ float sm[];
    float* Qs = sm;               // [64][256] linear
    float* Ks = sm + 64 * 256;    // [128][256] xor-swizzled rows (tile cols)

    const int qt = blockIdx.x;    // 0..31
    const int hb = blockIdx.y;    // 0..63
    const size_t base = (size_t)hb * SEQ * DIM;
    const int tid = threadIdx.x;
    const int w = tid >> 5, c = tid & 31;
    const int cx = c & 7;

    // K tile load: 128 rows x 64 float4 = 8192 tasks, 32 per thread
    auto load_ktile = [&](int kt) {
        #pragma unroll
        for (int i = 0; i < 32; i++) {
            int u = tid + i * 256;
            int r = u >> 6, k4 = u & 63;
            cpa16(&Ks[r * 256 + ((k4 ^ (r & 7)) << 2)],
                  &g_k[base + (size_t)(kt * 128 + r) * DIM + k4 * 4]);
        }
        asm volatile("cp.async.commit_group;");
    };

    // prefetch K tile 0 (async), then load Q tile 64x256
    load_ktile(0);
    #pragma unroll
    for (int i = 0; i < 16; i++) {
        int u = tid + i * 256;
        int r = u >> 6, k4 = u & 63;
        *(float4*)&Qs[r * 256 + k4 * 4] =
            *(const float4*)&g_q[base + (size_t)(qt * 64 + r) * DIM + k4 * 4];
    }

    ull o[8][4];                  // packed pairs covering dims 8c..8c+7
    #pragma unroll
    for (int i = 0; i < 8; i++)
        #pragma unroll
        for (int j = 0; j < 4; j++) o[i][j] = 0ull;
    float m[8], l[8];
    #pragma unroll
    for (int i = 0; i < 8; i++) { m[i] = -3.0e38f; l[i] = 0.f; }

    for (int kt = 0; kt < SEQ / 128; kt++) {
        asm volatile("cp.async.wait_group 0;");
        __syncthreads();          // tile kt (and Q on iter 0) visible

        // dense QK: lane computes s[rr][cols c, c+32, c+64, c+96]
        ull acc[8][4];
        #pragma unroll
        for (int rr = 0; rr < 8; rr++)
            #pragma unroll
            for (int j = 0; j < 4; j++) acc[rr][j] = 0ull;

        const float* kp0 = &Ks[c * 256];
        const float* kp1 = &Ks[(c + 32) * 256];   // same xor phase: &7 equal
        const float* kp2 = &Ks[(c + 64) * 256];
        const float* kp3 = &Ks[(c + 96) * 256];
        #pragma unroll 2
        for (int k4 = 0; k4 < 64; k4++) {
            int sc = (k4 ^ cx) << 2;
            ulonglong2 kv0 = *(const ulonglong2*)&kp0[sc];
            ulonglong2 kv1 = *(const ulonglong2*)&kp1[sc];
            ulonglong2 kv2 = *(const ulonglong2*)&kp2[sc];
            ulonglong2 kv3 = *(const ulonglong2*)&kp3[sc];
            #pragma unroll
            for (int rr = 0; rr < 8; rr++) {
                ulonglong2 qv = *(const ulonglong2*)&Qs[(w * 8 + rr) * 256 + k4 * 4];
                acc[rr][0] = ffma2(qv.x, kv0.x, acc[rr][0]);
                acc[rr][0] = ffma2(qv.y, kv0.y, acc[rr][0]);
                acc[rr][1] = ffma2(qv.x, kv1.x, acc[rr][1]);
                acc[rr][1] = ffma2(qv.y, kv1.y, acc[rr][1]);
                acc[rr][2] = ffma2(qv.x, kv2.x, acc[rr][2]);
                acc[rr][2] = ffma2(qv.y, kv2.y, acc[rr][2]);
                acc[rr][3] = ffma2(qv.x, kv3.x, acc[rr][3]);
                acc[rr][3] = ffma2(qv.y, kv3.y, acc[rr][3]);
            }
        }

        __syncthreads();          // all warps done reading Ks
        if (kt + 1 < SEQ / 128)
            load_ktile(kt + 1);   // overlaps the sparse phase below

        // sparse softmax + PV gather, per row (reads only regs + g_v)
        const float* vtile = &g_v[base + (size_t)(kt * 128) * DIM + c * 8];
        #pragma unroll
        for (int rr = 0; rr < 8; rr++) {
            float a, b;
            float s[4];
            upk2(acc[rr][0], a, b); s[0] = (a + b) * 0.0625f;
            upk2(acc[rr][1], a, b); s[1] = (a + b) * 0.0625f;
            upk2(acc[rr][2], a, b); s[2] = (a + b) * 0.0625f;
            upk2(acc[rr][3], a, b); s[3] = (a + b) * 0.0625f;
            float tm = fmaxf(fmaxf(s[0], s[1]), fmaxf(s[2], s[3]));
            #pragma unroll
            for (int off = 16; off > 0; off >>= 1)
                tm = fmaxf(tm, __shfl_xor_sync(0xffffffffu, tm, off));

            if (tm >= m[rr] - 35.0f) {            // warp-uniform
                float nm = fmaxf(m[rr], tm);
                if (nm > m[rr]) {                 // rescale only on max update
                    float fac = __expf(m[rr] - nm);
                    l[rr] *= fac;
                    ull f2 = pk2(fac, fac);
                    o[rr][0] = fmul2(o[rr][0], f2);
                    o[rr][1] = fmul2(o[rr][1], f2);
                    o[rr][2] = fmul2(o[rr][2], f2);
                    o[rr][3] = fmul2(o[rr][3], f2);
                    m[rr] = nm;
                }
                float thr = nm - 35.0f;
                #pragma unroll
                for (int j = 0; j < 4; j++) {
                    unsigned bal = __ballot_sync(0xffffffffu, s[j] >= thr);
                    while (bal) {
                        int ln = __ffs(bal) - 1; bal &= bal - 1;
                        float sv = __shfl_sync(0xffffffffu, s[j], ln);
                        float p = __expf(sv - nm);
                        l[rr] += p;
                        const ulonglong2* vr =
                            (const ulonglong2*)(vtile + (size_t)(ln + j * 32) * DIM);
                        ulonglong2 V0 = vr[0], V1 = vr[1];
                        ull pp = pk2(p, p);
                        o[rr][0] = ffma2(pp, V0.x, o[rr][0]);
                        o[rr][1] = ffma2(pp, V0.y, o[rr][1]);
                        o[rr][2] = ffma2(pp, V1.x, o[rr][2]);
                        o[rr][3] = ffma2(pp, V1.y, o[rr][3]);
                    }
                }
            }
        }
    }

    // ------------------------------------------------------------------
    // fused epilogue: out[r,n] += sum_d o_norm[r,d] * Cw[h*256+d, n]
    // ------------------------------------------------------------------
    const int h = hb >> 3;
    const int out_r0 = (hb & 7) * SEQ + qt * 64 + w * 8;

    float cw[8][8];               // [i dim-in-slice][n]
    const float* cwp = Cw + ((size_t)h * 256 + c * 8) * 8;
    #pragma unroll
    for (int i = 0; i < 8; i++) {
        float4 u0 = *(const float4*)&cwp[i * 8 + 0];
        float4 u1 = *(const float4*)&cwp[i * 8 + 4];
        cw[i][0] = u0.x; cw[i][1] = u0.y; cw[i][2] = u0.z; cw[i][3] = u0.w;
        cw[i][4] = u1.x; cw[i][5] = u1.y; cw[i][6] = u1.z; cw[i][7] = u1.w;
    }

    #pragma unroll
    for (int rr = 0; rr < 8; rr++) {
        float inv = 1.0f / l[rr];
        float v[8];
        upk2(o[rr][0], v[0], v[1]);
        upk2(o[rr][1], v[2], v[3]);
        upk2(o[rr][2], v[4], v[5]);
        upk2(o[rr][3], v[6], v[7]);
        float pn[8] = {};
        #pragma unroll
        for (int i = 0; i < 8; i++) {
            float ov = v[i] * inv;
            #pragma unroll
            for (int n = 0; n < 8; n++)
                pn[n] = fmaf(ov, cw[i][n], pn[n]);
        }
        #pragma unroll
        for (int n = 0; n < 8; n++) {
            #pragma unroll
            for (int off = 16; off > 0; off >>= 1)
                pn[n] += __shfl_xor_sync(0xffffffffu, pn[n], off);
        }
        if (c < 8)
            atomicAdd(&out[(size_t)(out_r0 + rr) * 8 + c], pn[c]);
    }
}

// ---------------------------------------------------------------------------
extern "C" void kernel_launch(void* const* d_in, const int* in_sizes, int n_in,
                              void* d_out, int out_size)
{
    const float* x    = (const float*)d_in[0];
    const float* lstm = (const float*)d_in[1];
    const float* Qw   = (const float*)d_in[2];
    const float* Qb   = (const float*)d_in[3];
    const float* Kw   = (const float*)d_in[4];
    const float* Kb   = (const float*)d_in[5];
    const float* Vw   = (const float*)d_in[6];
    const float* Vb   = (const float*)d_in[7];
    const float* Cw   = (const float*)d_in[8];
    const float* Cb   = (const float*)d_in[9];
    float* out = (float*)d_out;

    cudaFuncSetAttribute(flash_kernel, cudaFuncAttributeMaxDynamicSharedMemorySize, FLASH_SMEM);

    init_out_kernel<<<512, 256>>>(Cb, out);     // out[r,n] = Cb[n]
    proj_kernel<<<dim3(4, 256, 24), dim3(16, 16)>>>(x, lstm, Qw, Qb, Kw, Kb, Vw, Vb);
    flash_kernel<<<dim3(32, 64), 256, FLASH_SMEM>>>(Cw, out);
}